// round 11
// baseline (speedup 1.0000x reference)
#include <cuda_runtime.h>
#include <cuda_fp16.h>
#include <cuda_bf16.h>

#define D_IN   128
#define D_OUT  64
#define MAX_NODES 50048
#define MAX_EDGES 1048576

// Scratch (device globals; zero-initialized at module load).
// Invariant across calls/replays: g_head == 0 (aggregate resets after use).
__device__ __half g_h[(size_t)MAX_NODES * D_OUT];   // fp16 projected features
__device__ int    g_head[MAX_NODES];                // 0 = empty, else edge_id+1
__device__ int2   g_list[MAX_EDGES];                // {next_ptr, col}

// ---------------------------------------------------------------------------
// f32x2 packed helpers
// ---------------------------------------------------------------------------
__device__ __forceinline__ unsigned long long pk2(float a, float b) {
    unsigned long long r;
    asm("mov.b64 %0, {%1, %2};" : "=l"(r) : "f"(a), "f"(b));
    return r;
}
__device__ __forceinline__ void ffma2(unsigned long long& d,
                                      unsigned long long a,
                                      unsigned long long b) {
    asm("fma.rn.f32x2 %0, %1, %2, %3;" : "=l"(d) : "l"(a), "l"(b), "l"(d));
}
__device__ __forceinline__ float2 upk2(unsigned long long v) {
    float2 f;
    asm("mov.b64 {%0, %1}, %2;" : "=f"(f.x), "=f"(f.y) : "l"(v));
    return f;
}

// ---------------------------------------------------------------------------
// K1: linked-list bucket build (unchanged from R10).
// ---------------------------------------------------------------------------
__global__ void __launch_bounds__(256) build_kernel(const int* __restrict__ row,
                                                    const int* __restrict__ col, int E)
{
    int e = blockIdx.x * blockDim.x + threadIdx.x;
    if (e >= E) return;
    int r = __ldg(&row[e]);
    int c = __ldg(&col[e]);
    int old = atomicExch(&g_head[r], e + 1);
    g_list[e] = make_int2(old, c);
}

// ---------------------------------------------------------------------------
// K2: GEMM h = x @ W^T + b (f32x2 packed FMA), stores fp16 (unchanged).
// ---------------------------------------------------------------------------
__global__ void __launch_bounds__(128) gemm_kernel(
    const float* __restrict__ x, const float* __restrict__ W,
    const float* __restrict__ b, int N)
{
    __shared__ float4 xs[64][33];
    __shared__ float4 ws[64][33];

    const int tid = threadIdx.x;
    const int nb  = blockIdx.x * 64;

    const float4* W4 = (const float4*)W;
#pragma unroll
    for (int i = 0; i < 16; i++) {
        int lin = tid + 128 * i;
        int r = lin >> 5, c = lin & 31;
        ws[r][c] = W4[lin];
    }
    const float4* x4 = (const float4*)x;
#pragma unroll
    for (int i = 0; i < 16; i++) {
        int lin = tid + 128 * i;
        int r = lin >> 5, c = lin & 31;
        int node = nb + r;
        float4 v = make_float4(0.f, 0.f, 0.f, 0.f);
        if (node < N) v = x4[node * 32 + c];
        xs[r][c] = v;
    }
    __syncthreads();

    const int tx = tid & 15;
    const int ty = tid >> 4;

    unsigned long long acc[8][4];
#pragma unroll
    for (int i = 0; i < 8; i++)
#pragma unroll
        for (int j = 0; j < 4; j++) acc[i][j] = 0ull;

#pragma unroll 4
    for (int k = 0; k < 32; k++) {
        unsigned long long xlo[8], xhi[8], wlo[4], whi[4];
#pragma unroll
        for (int i = 0; i < 8; i++) {
            float4 v = xs[ty + 8 * i][k];
            xlo[i] = pk2(v.x, v.y);
            xhi[i] = pk2(v.z, v.w);
        }
#pragma unroll
        for (int j = 0; j < 4; j++) {
            float4 v = ws[tx + 16 * j][k];
            wlo[j] = pk2(v.x, v.y);
            whi[j] = pk2(v.z, v.w);
        }
#pragma unroll
        for (int i = 0; i < 8; i++) {
#pragma unroll
            for (int j = 0; j < 4; j++) {
                ffma2(acc[i][j], xlo[i], wlo[j]);
                ffma2(acc[i][j], xhi[i], whi[j]);
            }
        }
    }

    float bias[4];
#pragma unroll
    for (int j = 0; j < 4; j++) bias[j] = __ldg(&b[tx + 16 * j]);

#pragma unroll
    for (int i = 0; i < 8; i++) {
        int node = nb + ty + 8 * i;
        if (node < N) {
#pragma unroll
            for (int j = 0; j < 4; j++) {
                float2 p = upk2(acc[i][j]);
                g_h[(size_t)node * D_OUT + tx + 16 * j] =
                    __float2half(p.x + p.y + bias[j]);
            }
        }
    }
}

// ---------------------------------------------------------------------------
// K3: aggregate via 4 concurrent list chases per warp.
// Warp w handles nodes 4w..4w+3; lane 0 chases all 4 chains (MLP=4),
// all lanes gather one 128B fp16 line per live chain per iteration.
// ---------------------------------------------------------------------------
__global__ void __launch_bounds__(256) aggregate_kernel(float* __restrict__ out, int N)
{
    int warp = (blockIdx.x * blockDim.x + threadIdx.x) >> 5;
    int lane = threadIdx.x & 31;
    int n0 = warp * 4;
    if (n0 >= N) return;

    const __half2* h2 = (const __half2*)g_h;

    int   ptr[4];
    int2  cur[4];
    float2 acc[4];
    int   deg[4];

#pragma unroll
    for (int q = 0; q < 4; q++) {
        int node = n0 + q;
        ptr[q] = (node < N) ? __ldg(&g_head[node]) : 0;
        acc[q] = make_float2(0.f, 0.f);
        deg[q] = 0;
        cur[q] = make_int2(0, 0);
    }
    if (lane == 0) {
#pragma unroll
        for (int q = 0; q < 4; q++) {
            int node = n0 + q;
            if (ptr[q]) {
                g_head[node] = 0;                   // restore invariant
                cur[q] = __ldg(&g_list[ptr[q] - 1]);
            }
        }
    }

    while (ptr[0] | ptr[1] | ptr[2] | ptr[3]) {
        int np[4], cv[4];
#pragma unroll
        for (int q = 0; q < 4; q++) {
            np[q] = __shfl_sync(~0u, cur[q].x, 0);
            cv[q] = __shfl_sync(~0u, cur[q].y, 0);
        }
        // issue next chase loads (independent, MLP=4) before consuming gathers
        int2 nxt[4];
#pragma unroll
        for (int q = 0; q < 4; q++) nxt[q] = make_int2(0, 0);
        if (lane == 0) {
#pragma unroll
            for (int q = 0; q < 4; q++)
                if (ptr[q] && np[q]) nxt[q] = __ldg(&g_list[np[q] - 1]);
        }
        // gathers (independent, up to 4 in flight per lane)
#pragma unroll
        for (int q = 0; q < 4; q++) {
            if (ptr[q]) {
                float2 f = __half22float2(h2[cv[q] * 32 + lane]);
                acc[q].x += f.x;
                acc[q].y += f.y;
                deg[q]++;
            }
        }
#pragma unroll
        for (int q = 0; q < 4; q++) {
            ptr[q] = ptr[q] ? np[q] : 0;
            cur[q] = nxt[q];
        }
    }

#pragma unroll
    for (int q = 0; q < 4; q++) {
        int node = n0 + q;
        if (node < N) {
            float d = fmaxf((float)deg[q], 1.0f);
            float2 a = acc[q];
            a.x /= d; a.y /= d;
            ((float2*)out)[node * 32 + lane] = a;
        }
    }
}

// ---------------------------------------------------------------------------
extern "C" void kernel_launch(void* const* d_in, const int* in_sizes, int n_in,
                              void* d_out, int out_size)
{
    const float* x   = (const float*)d_in[0];
    const float* W   = (const float*)d_in[1];
    const float* b   = (const float*)d_in[2];
    const int*   row = (const int*)d_in[3];
    const int*   col = (const int*)d_in[4];
    float* out = (float*)d_out;

    int N = in_sizes[0] / D_IN;   // 50000
    int E = in_sizes[3];          // 800000

    build_kernel<<<(E + 255) / 256, 256>>>(row, col, E);
    gemm_kernel<<<(N + 63) / 64, 128>>>(x, W, b, N);

    int nwarps = (N + 3) / 4;                       // one warp per 4 nodes
    long long threads = (long long)nwarps * 32;
    aggregate_kernel<<<(int)((threads + 255) / 256), 256>>>(out, N);
}

// round 12
// speedup vs baseline: 1.0535x; 1.0535x over previous
#include <cuda_runtime.h>
#include <cuda_fp16.h>
#include <cuda_bf16.h>
#include <mma.h>

using namespace nvcuda;

#define D_IN   128
#define D_OUT  64
#define MAX_NODES 50048
#define MAX_EDGES 1048576
#define TILE_M 128

// Scratch (device globals; zero-initialized at module load).
// Invariant across calls/replays: g_head == 0 (aggregate resets after use).
__device__ __half g_h[(size_t)MAX_NODES * D_OUT];   // fp16 projected features
__device__ int    g_head[MAX_NODES];                // 0 = empty, else edge_id+1
__device__ int2   g_list[MAX_EDGES];                // {next_ptr, col}

// ---------------------------------------------------------------------------
// K1: linked-list bucket build (unchanged from R10).
// ---------------------------------------------------------------------------
__global__ void __launch_bounds__(256) build_kernel(const int* __restrict__ row,
                                                    const int* __restrict__ col, int E)
{
    int e = blockIdx.x * blockDim.x + threadIdx.x;
    if (e >= E) return;
    int r = __ldg(&row[e]);
    int c = __ldg(&col[e]);
    int old = atomicExch(&g_head[r], e + 1);
    g_list[e] = make_int2(old, c);
}

// ---------------------------------------------------------------------------
// K2: GEMM h = x @ W^T + b via wmma (fp16 inputs, fp32 accumulate).
// Block: 256 threads = 8 warps; tile 128 nodes x 64 outs.
// Warp w computes rows [16w, 16w+16) x all 64 cols (4 fragments, 8 k-steps).
// smem: xs fp16 [128][128] (32KB) + ws fp16 [64][128] (16KB); epilogue reuses
// xs region as fp32 [128][64] staging.
// ---------------------------------------------------------------------------
__global__ void __launch_bounds__(256) gemm_kernel(
    const float* __restrict__ x, const float* __restrict__ W,
    const float* __restrict__ b, int N)
{
    __shared__ __align__(16) char smraw[49152];
    __half* xs = (__half*)smraw;                 // [128][128] fp16, 32KB
    __half* ws = (__half*)(smraw + 32768);       // [64][128]  fp16, 16KB
    float*  cs = (float*)smraw;                  // [128][64]  fp32 (epilogue, reuses xs)

    const int tid = threadIdx.x;
    const int w   = tid >> 5;
    const int nb  = blockIdx.x * TILE_M;

    // Load W (64x128 fp32 -> fp16 smem): 2048 float4, 8 per thread.
    const float4* W4 = (const float4*)W;
#pragma unroll
    for (int i = 0; i < 8; i++) {
        int lin = tid + 256 * i;                 // 0..2047
        float4 v = W4[lin];
        __half2* dst = (__half2*)ws + lin * 2;
        dst[0] = __floats2half2_rn(v.x, v.y);
        dst[1] = __floats2half2_rn(v.z, v.w);
    }
    // Load x tile (128x128 fp32 -> fp16 smem): 4096 float4, 16 per thread.
    const float4* x4 = (const float4*)x;
#pragma unroll
    for (int i = 0; i < 16; i++) {
        int lin = tid + 256 * i;                 // 0..4095
        int r = lin >> 5;
        int node = nb + r;
        float4 v = make_float4(0.f, 0.f, 0.f, 0.f);
        if (node < N) v = x4[node * 32 + (lin & 31)];
        __half2* dst = (__half2*)xs + lin * 2;
        dst[0] = __floats2half2_rn(v.x, v.y);
        dst[1] = __floats2half2_rn(v.z, v.w);
    }
    __syncthreads();

    // MMA: warp w -> rows [16w, 16w+16), 4 n-fragments of 16 cols, 8 k-steps.
    wmma::fragment<wmma::accumulator, 16, 16, 16, float> acc[4];
#pragma unroll
    for (int n = 0; n < 4; n++) wmma::fill_fragment(acc[n], 0.0f);

#pragma unroll
    for (int k = 0; k < 8; k++) {
        wmma::fragment<wmma::matrix_a, 16, 16, 16, __half, wmma::row_major> af;
        wmma::load_matrix_sync(af, xs + (w * 16) * 128 + k * 16, 128);
#pragma unroll
        for (int n = 0; n < 4; n++) {
            wmma::fragment<wmma::matrix_b, 16, 16, 16, __half, wmma::col_major> bf;
            wmma::load_matrix_sync(bf, ws + (n * 16) * 128 + k * 16, 128);
            wmma::mma_sync(acc[n], af, bf, acc[n]);
        }
    }

    __syncthreads();   // done reading xs; reuse as fp32 staging
#pragma unroll
    for (int n = 0; n < 4; n++)
        wmma::store_matrix_sync(cs + (w * 16) * 64 + n * 16, acc[n], 64,
                                wmma::mem_row_major);
    __syncthreads();

    // Epilogue: cs [128][64] fp32 + bias -> g_h fp16. 2048 float4, 8/thread.
    const float4* b4 = (const float4*)b;
#pragma unroll
    for (int i = 0; i < 8; i++) {
        int lin = tid + 256 * i;                 // 0..2047
        int r = lin >> 4, c4 = lin & 15;
        int node = nb + r;
        if (node < N) {
            float4 v = ((const float4*)cs)[lin];
            float4 bb = __ldg(&b4[c4]);
            __half2 lo = __floats2half2_rn(v.x + bb.x, v.y + bb.y);
            __half2 hi = __floats2half2_rn(v.z + bb.z, v.w + bb.w);
            __half2* dst = (__half2*)&g_h[(size_t)node * D_OUT + c4 * 4];
            dst[0] = lo;
            dst[1] = hi;
        }
    }
}

// ---------------------------------------------------------------------------
// K3: aggregate via list chase (R10 form: one warp per node, single chain,
// software-pipelined chase) + normalize + write + reset head.
// ---------------------------------------------------------------------------
__global__ void __launch_bounds__(256) aggregate_kernel(float* __restrict__ out, int N)
{
    int node = (blockIdx.x * blockDim.x + threadIdx.x) >> 5;
    int lane = threadIdx.x & 31;
    if (node >= N) return;

    int ptr = __ldg(&g_head[node]);
    if (lane == 0 && ptr != 0) g_head[node] = 0;   // restore invariant

    const __half2* h2 = (const __half2*)g_h;
    float2 acc = make_float2(0.f, 0.f);
    int deg = 0;

    int2 cur = make_int2(0, 0);
    if (lane == 0 && ptr != 0) cur = __ldg(&g_list[ptr - 1]);

    while (ptr != 0) {
        int nptr = __shfl_sync(~0u, cur.x, 0);
        int colv = __shfl_sync(~0u, cur.y, 0);

        int2 nxt = make_int2(0, 0);
        if (lane == 0 && nptr != 0) nxt = __ldg(&g_list[nptr - 1]);

        float2 f = __half22float2(h2[colv * 32 + lane]);
        acc.x += f.x;
        acc.y += f.y;
        deg++;

        ptr = nptr;
        cur = nxt;
    }

    float d = fmaxf((float)deg, 1.0f);
    acc.x /= d; acc.y /= d;
    ((float2*)out)[node * 32 + lane] = acc;
}

// ---------------------------------------------------------------------------
extern "C" void kernel_launch(void* const* d_in, const int* in_sizes, int n_in,
                              void* d_out, int out_size)
{
    const float* x   = (const float*)d_in[0];
    const float* W   = (const float*)d_in[1];
    const float* b   = (const float*)d_in[2];
    const int*   row = (const int*)d_in[3];
    const int*   col = (const int*)d_in[4];
    float* out = (float*)d_out;

    int N = in_sizes[0] / D_IN;   // 50000
    int E = in_sizes[3];          // 800000

    build_kernel<<<(E + 255) / 256, 256>>>(row, col, E);
    gemm_kernel<<<(N + TILE_M - 1) / TILE_M, 256>>>(x, W, b, N);

    long long total = (long long)N * 32;
    aggregate_kernel<<<(int)((total + 255) / 256), 256>>>(out, N);
}

// round 13
// speedup vs baseline: 1.0738x; 1.0193x over previous
#include <cuda_runtime.h>
#include <cuda_fp16.h>
#include <cuda_bf16.h>
#include <mma.h>

using namespace nvcuda;

#define D_IN   128
#define D_OUT  64
#define MAX_NODES 50048
#define MAX_EDGES 1048576
#define TILE_M 64

// Scratch (device globals; zero-initialized at module load).
// Invariant across calls/replays: g_head == 0 (aggregate resets after use).
__device__ __half g_h[(size_t)MAX_NODES * D_OUT];   // fp16 projected features
__device__ int    g_head[MAX_NODES];                // 0 = empty, else edge_id+1
__device__ int2   g_list[MAX_EDGES];                // {next_ptr, col}

// ---------------------------------------------------------------------------
// K1: fused GEMM + linked-list build, split by blockIdx (no inter-dependence).
// Blocks [0, gemmb): wmma GEMM tile (64 nodes x 64 outs, 128 thr, 32KB smem).
// Blocks [gemmb, ...): build 128 edges each.
// ---------------------------------------------------------------------------
__global__ void __launch_bounds__(128) fused_gb_kernel(
    const float* __restrict__ x, const float* __restrict__ W,
    const float* __restrict__ b, const int* __restrict__ row,
    const int* __restrict__ col, int N, int E, int gemmb)
{
    __shared__ __align__(16) char smraw[32768];

    const int tid = threadIdx.x;

    if (blockIdx.x >= gemmb) {
        // ---------------- build path ----------------
        int e = (blockIdx.x - gemmb) * 128 + tid;
        if (e < E) {
            int r = __ldg(&row[e]);
            int c = __ldg(&col[e]);
            int old = atomicExch(&g_head[r], e + 1);
            g_list[e] = make_int2(old, c);
        }
        return;
    }

    // ---------------- gemm path ----------------
    __half* xs = (__half*)smraw;                 // [64][128] fp16, 16KB
    __half* ws = (__half*)(smraw + 16384);       // [64][128] fp16, 16KB
    float*  cs = (float*)smraw;                  // [64][64]  fp32 epilogue (reuses xs)

    const int w  = tid >> 5;
    const int nb = blockIdx.x * TILE_M;

    // Load W (64x128 fp32 -> fp16): 2048 float4, 16 per thread.
    const float4* W4 = (const float4*)W;
#pragma unroll
    for (int i = 0; i < 16; i++) {
        int lin = tid + 128 * i;                 // 0..2047
        float4 v = W4[lin];
        __half2* dst = (__half2*)ws + lin * 2;
        dst[0] = __floats2half2_rn(v.x, v.y);
        dst[1] = __floats2half2_rn(v.z, v.w);
    }
    // Load x tile (64x128 fp32 -> fp16): 2048 float4, 16 per thread.
    const float4* x4 = (const float4*)x;
#pragma unroll
    for (int i = 0; i < 16; i++) {
        int lin = tid + 128 * i;                 // 0..2047
        int r = lin >> 5;
        int node = nb + r;
        float4 v = make_float4(0.f, 0.f, 0.f, 0.f);
        if (node < N) v = x4[node * 32 + (lin & 31)];
        __half2* dst = (__half2*)xs + lin * 2;
        dst[0] = __floats2half2_rn(v.x, v.y);
        dst[1] = __floats2half2_rn(v.z, v.w);
    }
    __syncthreads();

    // MMA: warp w -> rows [16w, 16w+16), 4 n-fragments of 16 cols, 8 k-steps.
    wmma::fragment<wmma::accumulator, 16, 16, 16, float> acc[4];
#pragma unroll
    for (int n = 0; n < 4; n++) wmma::fill_fragment(acc[n], 0.0f);

#pragma unroll
    for (int k = 0; k < 8; k++) {
        wmma::fragment<wmma::matrix_a, 16, 16, 16, __half, wmma::row_major> af;
        wmma::load_matrix_sync(af, xs + (w * 16) * 128 + k * 16, 128);
#pragma unroll
        for (int n = 0; n < 4; n++) {
            wmma::fragment<wmma::matrix_b, 16, 16, 16, __half, wmma::col_major> bf;
            wmma::load_matrix_sync(bf, ws + (n * 16) * 128 + k * 16, 128);
            wmma::mma_sync(acc[n], af, bf, acc[n]);
        }
    }

    __syncthreads();   // done reading xs; reuse as fp32 staging
#pragma unroll
    for (int n = 0; n < 4; n++)
        wmma::store_matrix_sync(cs + (w * 16) * 64 + n * 16, acc[n], 64,
                                wmma::mem_row_major);
    __syncthreads();

    // Epilogue: cs [64][64] fp32 + bias -> g_h fp16. 1024 float4, 8/thread.
    const float4* b4 = (const float4*)b;
#pragma unroll
    for (int i = 0; i < 8; i++) {
        int lin = tid + 128 * i;                 // 0..1023
        int r = lin >> 4, c4 = lin & 15;
        int node = nb + r;
        if (node < N) {
            float4 v = ((const float4*)cs)[lin];
            float4 bb = __ldg(&b4[c4]);
            __half2 lo = __floats2half2_rn(v.x + bb.x, v.y + bb.y);
            __half2 hi = __floats2half2_rn(v.z + bb.z, v.w + bb.w);
            __half2* dst = (__half2*)&g_h[(size_t)node * D_OUT + c4 * 4];
            dst[0] = lo;
            dst[1] = hi;
        }
    }
}

// ---------------------------------------------------------------------------
// K2: aggregate via list chase (one warp per node, software-pipelined chase)
// + normalize + write + reset head.
// ---------------------------------------------------------------------------
__global__ void __launch_bounds__(256) aggregate_kernel(float* __restrict__ out, int N)
{
    int node = (blockIdx.x * blockDim.x + threadIdx.x) >> 5;
    int lane = threadIdx.x & 31;
    if (node >= N) return;

    int ptr = __ldg(&g_head[node]);
    if (lane == 0 && ptr != 0) g_head[node] = 0;   // restore invariant

    const __half2* h2 = (const __half2*)g_h;
    float2 acc = make_float2(0.f, 0.f);
    int deg = 0;

    int2 cur = make_int2(0, 0);
    if (lane == 0 && ptr != 0) cur = __ldg(&g_list[ptr - 1]);

    while (ptr != 0) {
        int nptr = __shfl_sync(~0u, cur.x, 0);
        int colv = __shfl_sync(~0u, cur.y, 0);

        int2 nxt = make_int2(0, 0);
        if (lane == 0 && nptr != 0) nxt = __ldg(&g_list[nptr - 1]);

        float2 f = __half22float2(h2[colv * 32 + lane]);
        acc.x += f.x;
        acc.y += f.y;
        deg++;

        ptr = nptr;
        cur = nxt;
    }

    float d = fmaxf((float)deg, 1.0f);
    acc.x /= d; acc.y /= d;
    ((float2*)out)[node * 32 + lane] = acc;
}

// ---------------------------------------------------------------------------
extern "C" void kernel_launch(void* const* d_in, const int* in_sizes, int n_in,
                              void* d_out, int out_size)
{
    const float* x   = (const float*)d_in[0];
    const float* W   = (const float*)d_in[1];
    const float* b   = (const float*)d_in[2];
    const int*   row = (const int*)d_in[3];
    const int*   col = (const int*)d_in[4];
    float* out = (float*)d_out;

    int N = in_sizes[0] / D_IN;   // 50000
    int E = in_sizes[3];          // 800000

    int gemmb  = (N + TILE_M - 1) / TILE_M;      // 782
    int buildb = (E + 127) / 128;                // 6250

    fused_gb_kernel<<<gemmb + buildb, 128>>>(x, W, b, row, col, N, E, gemmb);

    long long total = (long long)N * 32;
    aggregate_kernel<<<(int)((total + 255) / 256), 256>>>(out, N);
}